// round 9
// baseline (speedup 1.0000x reference)
#include <cuda_runtime.h>

#define BS 8
#define LQ 2049
#define NC 32
#define NH 16
#define KS 5
#define NL 4
#define NPOS (BS*LQ)            // 16392
#define TILE 16
#define NTILE 1025              // ceil(NPOS/16)
#define KA 584                  // 512 Gsum + 32 fsum + 32 enc + 1 one + 7 pad
#define KHALF (KA/2)            // 292
#define TILE_ELEMS (KA*NC)      // 18688
#define ASTRIDE 596             // padded A row stride
#define FUSED_GRID 740          // 5 blocks x 148 SMs (work-stealing, any occupancy safe)

#define BUILD_BLOCKS 2049       // NPOS*NC/256
#define MLPB 321                // per-layer MLP blocks
#define WC_BLOCKS 292           // NL*TILE_ELEMS/256
#define PREP_BLOCKS (BUILD_BLOCKS + NL*MLPB + WC_BLOCKS)

// -------- device scratch --------
__device__ __align__(16) float g_times[BS*LQ];
__device__ __align__(16) float g_enc[NPOS*NC];
__device__ __align__(16) float g_raw[2][NTILE*TILE*NC];   // ping-pong
__device__ __align__(16) float g_H2[NL*NPOS*KS*NH];       // 21 MB, all layers
__device__ __align__(16) float g_Wc[NL*TILE_ELEMS];
__device__ __align__(16) float g_psum[NTILE*NC];
__device__ __align__(16) float g_psq[NTILE*NC];
__device__ __align__(16) float g_bn[2*NC];
__device__ int g_maxtype;
__device__ int g_ticket[NL];
__device__ int g_done[NL];

__device__ __forceinline__ float lrelu(float x) { return x >= 0.f ? x : 0.1f*x; }

// -------- prep 1: max type, times, counter reset --------
__global__ void k_max(const float* __restrict__ et, const int* __restrict__ types) {
    __shared__ int sm[1024];
    int t = threadIdx.x, m = 0;
    for (int i = t; i < BS*2048; i += 1024) m = max(m, types[i]);
    sm[t] = m;
    for (int s = 512; s > 0; s >>= 1) {
        __syncthreads();
        if (t < s) sm[t] = max(sm[t], sm[t+s]);
    }
    __syncthreads();
    if (t == 0) {
        g_maxtype = sm[0];
        #pragma unroll
        for (int i = 0; i < NL; i++) { g_ticket[i] = 0; g_done[i] = 0; }
    }
    for (int i = t; i < NPOS; i += 1024) {
        int b = i / LQ, l = i - b*LQ;
        g_times[i] = (l == 0) ? 0.f : et[b*2048 + l - 1];
    }
}

// -------- prep 2 (merged): enc build | all-layer MLP | Wc build --------
__global__ __launch_bounds__(256) void k_prep(
        const int* __restrict__ ty, const float* __restrict__ emb,
        const float* __restrict__ k1W, const float* __restrict__ k1b,
        const float* __restrict__ k2W, const float* __restrict__ k2b,
        const float* __restrict__ k3W, const float* __restrict__ k3b,
        const float* __restrict__ skipW, const float* __restrict__ skipb) {
    int bid = blockIdx.x;
    int t = threadIdx.x;

    if (bid < BUILD_BLOCKS) {
        // ---- embedded features ----
        int idx = bid*256 + t;
        if (idx >= NPOS*NC) return;
        int pos = idx >> 5, c = idx & 31;
        int b = pos / LQ, l = pos - b*LQ;
        int tp = (l == 0) ? (g_maxtype + 1) : ty[b*2048 + l - 1];
        g_enc[idx] = (tp == 0) ? 0.f : emb[tp*NC + c];
        return;
    }
    if (bid < BUILD_BLOCKS + NL*MLPB) {
        // ---- kernel MLPs: H2[layer][pos][k][16] ----
        int idx2 = bid - BUILD_BLOCKS;
        int layer = idx2 / MLPB;
        int blk = idx2 - layer*MLPB;
        int dil = 1 << layer;
        __shared__ float sk1[NH], sk1b[NH], sk2[NH*NH], sk2b[NH];
        if (t < NH) { sk1[t] = k1W[layer*NH + t]; sk1b[t] = k1b[layer*NH + t];
                      sk2b[t] = k2b[layer*NH + t]; }
        sk2[t] = k2W[layer*NH*NH + t];
        __syncthreads();
        int idx = blk*256 + t;
        if (idx >= NPOS*KS) return;
        int pos = idx / KS, k = idx - pos*KS;
        int b = pos / LQ, l = pos - b*LQ;
        float out[NH];
        bool valid = false;
        int j = l - k*dil;
        float tl = g_times[pos];
        if (j >= 0 && tl != 0.f) {
            float tj = g_times[b*LQ + j];
            if (tj != 0.f) {
                valid = true;
                float dt = tl - tj;
                float h1[NH];
                #pragma unroll
                for (int h = 0; h < NH; h++) h1[h] = lrelu(fmaf(dt, sk1[h], sk1b[h]));
                #pragma unroll
                for (int hh = 0; hh < NH; hh++) {
                    float s = sk2b[hh];
                    #pragma unroll
                    for (int x = 0; x < NH; x++) s = fmaf(h1[x], sk2[x*NH + hh], s);
                    out[hh] = lrelu(s);
                }
            }
        }
        if (!valid) {
            #pragma unroll
            for (int h = 0; h < NH; h++) out[h] = 0.f;
        }
        float* dst = g_H2 + (size_t)((layer*NPOS + pos)*KS + k)*NH;
        #pragma unroll
        for (int q = 0; q < 4; q++)
            *reinterpret_cast<float4*>(dst + 4*q) =
                make_float4(out[4*q], out[4*q+1], out[4*q+2], out[4*q+3]);
        return;
    }
    // ---- combined weight matrix Wc[layer][584][32] ----
    {
        int idx = (bid - BUILD_BLOCKS - NL*MLPB)*256 + t;
        if (idx >= NL*TILE_ELEMS) return;
        int layer = idx / TILE_ELEMS;
        int rem = idx - layer*TILE_ELEMS;
        int r = rem >> 5, d = rem & 31;
        float v;
        if (r < 512)      v = k3W[layer*16384 + r*32 + d];
        else if (r < 544) v = k3b[layer*1024 + (r-512)*32 + d];
        else if (r < 576) v = skipW[layer*1024 + (r-544)*32 + d];
        else if (r == 576) v = skipb[layer*32 + d];
        else v = 0.f;
        g_Wc[idx] = v;
    }
}

// -------- fused: work-stealing tiles + phase A + f32x2 GEMM + last-block stats
__global__ __launch_bounds__(256) void k_fused(int layer, int dil, int first,
        const float* __restrict__ gamma, const float* __restrict__ beta) {
    __shared__ float s_bn[64];
    __shared__ __align__(16) float s_A[TILE*ASTRIDE];     // 38144 B
    __shared__ __align__(16) float s_red[TILE*NC];
    __shared__ __align__(16) float s_ps[TILE*NC], s_ps2[TILE*NC];
    __shared__ int s_flag;
    int t = threadIdx.x;
    int lane = t & 31, warp = t >> 5;
    const float* raw_in = g_raw[(layer + 1) & 1];
    float* raw_out = g_raw[layer & 1];

    if (!first && t < 64) s_bn[t] = g_bn[t];

    for (;;) {
        if (t == 0) s_flag = atomicAdd(&g_ticket[layer], 1);
        __syncthreads();
        int tile = s_flag;
        if (tile >= NTILE) break;

        // ---- phase A: 8 warps x 2 positions; lane = channel c ----
        #pragma unroll
        for (int wp = 0; wp < 2; wp++) {
            int p = warp*2 + wp;
            int pos = tile*TILE + p;
            float G[NH];
            #pragma unroll
            for (int h = 0; h < NH; h++) G[h] = 0.f;
            float fs = 0.f, en = 0.f, one = 0.f;
            if (pos < NPOS) {
                one = 1.f;
                int b = pos / LQ, l = pos - b*LQ;
                float tl = g_times[pos];
                if (first) en = g_enc[pos*NC + lane];
                else {
                    float v = fmaf(raw_in[pos*NC + lane], s_bn[lane], s_bn[32 + lane]);
                    en = v >= 0.f ? v : 0.1f*v;
                }
                if (tl != 0.f) {
                    const float* h2p = g_H2 + (size_t)((layer*NPOS + pos)*KS)*NH;
                    for (int k = 0; k < KS; k++) {
                        int j = l - k*dil;
                        if (j < 0) break;
                        float tj = g_times[b*LQ + j];
                        if (tj != 0.f) {
                            int pj = pos - k*dil;
                            float g;
                            if (first) g = g_enc[pj*NC + lane];
                            else {
                                float v = fmaf(raw_in[pj*NC + lane], s_bn[lane], s_bn[32 + lane]);
                                g = v >= 0.f ? v : 0.1f*v;
                            }
                            fs += g;
                            float4 h0 = *reinterpret_cast<const float4*>(h2p + k*NH + 0);
                            float4 h1 = *reinterpret_cast<const float4*>(h2p + k*NH + 4);
                            float4 h2 = *reinterpret_cast<const float4*>(h2p + k*NH + 8);
                            float4 h3 = *reinterpret_cast<const float4*>(h2p + k*NH + 12);
                            G[0] = fmaf(h0.x, g, G[0]);  G[1] = fmaf(h0.y, g, G[1]);
                            G[2] = fmaf(h0.z, g, G[2]);  G[3] = fmaf(h0.w, g, G[3]);
                            G[4] = fmaf(h1.x, g, G[4]);  G[5] = fmaf(h1.y, g, G[5]);
                            G[6] = fmaf(h1.z, g, G[6]);  G[7] = fmaf(h1.w, g, G[7]);
                            G[8] = fmaf(h2.x, g, G[8]);  G[9] = fmaf(h2.y, g, G[9]);
                            G[10] = fmaf(h2.z, g, G[10]); G[11] = fmaf(h2.w, g, G[11]);
                            G[12] = fmaf(h3.x, g, G[12]); G[13] = fmaf(h3.y, g, G[13]);
                            G[14] = fmaf(h3.z, g, G[14]); G[15] = fmaf(h3.w, g, G[15]);
                        }
                    }
                }
            }
            float* row = s_A + p*ASTRIDE;
            #pragma unroll
            for (int h = 0; h < NH; h++) row[h*32 + lane] = G[h];
            row[512 + lane] = fs;
            row[544 + lane] = en;
            if (lane == 0) row[576] = one;
            if (lane < 7)  row[577 + lane] = 0.f;
        }
        __syncthreads();

        // ---- GEMM: 2-way K-split, packed f32x2 FMA ----
        int ks = t >> 7;           // 0..1
        int ty = (t >> 3) & 15;    // pos in tile
        int tx = t & 7;            // d0 = 4*tx
        const float* Ap = s_A + ty*ASTRIDE + ks*KHALF;
        const float* Wl = g_Wc + layer*TILE_ELEMS + ks*KHALF*NC + 4*tx;
        unsigned long long acc0 = 0ULL, acc1 = 0ULL;
        #pragma unroll 4
        for (int kk = 0; kk < KHALF/4; kk++) {         // 73 iterations
            float4 a = *reinterpret_cast<const float4*>(Ap + kk*4);
            #pragma unroll
            for (int r = 0; r < 4; r++) {
                ulonglong2 w = *reinterpret_cast<const ulonglong2*>(Wl + (4*kk + r)*NC);
                float av = (r == 0) ? a.x : (r == 1) ? a.y : (r == 2) ? a.z : a.w;
                unsigned long long ap2;
                asm("mov.b64 %0, {%1, %1};" : "=l"(ap2) : "f"(av));
                asm("fma.rn.f32x2 %0, %1, %2, %0;" : "+l"(acc0) : "l"(ap2), "l"(w.x));
                asm("fma.rn.f32x2 %0, %1, %2, %0;" : "+l"(acc1) : "l"(ap2), "l"(w.y));
            }
        }
        float r0, r1, r2, r3;
        asm("mov.b64 {%0, %1}, %2;" : "=f"(r0), "=f"(r1) : "l"(acc0));
        asm("mov.b64 {%0, %1}, %2;" : "=f"(r2), "=f"(r3) : "l"(acc1));

        if (ks == 1)
            *reinterpret_cast<float4*>(&s_red[ty*32 + 4*tx]) = make_float4(r0, r1, r2, r3);
        __syncthreads();
        if (ks == 0) {
            float4 o = *reinterpret_cast<const float4*>(&s_red[ty*32 + 4*tx]);
            r0 += o.x; r1 += o.y; r2 += o.z; r3 += o.w;
            *reinterpret_cast<float4*>(raw_out + (size_t)(tile*TILE + ty)*NC + 4*tx) =
                make_float4(r0, r1, r2, r3);
            *reinterpret_cast<float4*>(&s_ps [ty*32 + 4*tx]) = make_float4(r0, r1, r2, r3);
            *reinterpret_cast<float4*>(&s_ps2[ty*32 + 4*tx]) =
                make_float4(r0*r0, r1*r1, r2*r2, r3*r3);
        }
        __syncthreads();
        if (t < 32) {
            float s = 0.f, s2 = 0.f;
            #pragma unroll
            for (int r = 0; r < TILE; r++) { s += s_ps[r*32 + t]; s2 += s_ps2[r*32 + t]; }
            g_psum[tile*32 + t] = s;
            g_psq [tile*32 + t] = s2;
        }
        // loop-top syncthreads orders s_ps reads before next iteration's writes
    }

    // ---- done-count; last block computes BN stats (deterministic order) ----
    __threadfence();
    __syncthreads();
    if (t == 0) s_flag = atomicAdd(&g_done[layer], 1);
    __syncthreads();
    if (s_flag == (int)gridDim.x - 1) {
        __threadfence();
        float* ss  = s_ps;    // reuse smem: [8][33]
        float* ss2 = s_ps2;
        int r = t >> 5, n = t & 31;
        float s = 0.f, s2 = 0.f;
        for (int b = r; b < NTILE; b += 8) {
            s += g_psum[b*32 + n];
            s2 += g_psq[b*32 + n];
        }
        ss[r*33 + n] = s; ss2[r*33 + n] = s2;
        __syncthreads();
        if (t < 32) {
            float fs = 0.f, fs2 = 0.f;
            #pragma unroll
            for (int i = 0; i < 8; i++) { fs += ss[i*33 + t]; fs2 += ss2[i*33 + t]; }
            float inv = 1.0f / (float)NPOS;
            float mu = fs * inv;
            float var = fs2 * inv - mu*mu;
            float scale = rsqrtf(var + 1e-5f) * gamma[layer*32 + t];
            g_bn[t]      = scale;
            g_bn[32 + t] = beta[layer*32 + t] - mu*scale;
        }
    }
}

// -------- final apply: BN + leaky ReLU -> output --------
__global__ void k_apply(float* dst, int buf) {
    int idx = blockIdx.x*blockDim.x + threadIdx.x;
    if (idx >= NPOS*NC) return;
    int n = idx & 31;
    float v = fmaf(g_raw[buf][idx], g_bn[n], g_bn[32 + n]);
    dst[idx] = v >= 0.f ? v : 0.1f*v;
}

extern "C" void kernel_launch(void* const* d_in, const int* in_sizes, int n_in,
                              void* d_out, int out_size) {
    const float* event_times = (const float*)d_in[0];
    const int*   event_types = (const int*)  d_in[1];
    const float* emb   = (const float*)d_in[2];
    const float* k1W   = (const float*)d_in[3];
    const float* k1b   = (const float*)d_in[4];
    const float* k2W   = (const float*)d_in[5];
    const float* k2b   = (const float*)d_in[6];
    const float* k3W   = (const float*)d_in[7];
    const float* k3b   = (const float*)d_in[8];
    const float* skipW = (const float*)d_in[9];
    const float* skipb = (const float*)d_in[10];
    const float* gamma = (const float*)d_in[11];
    const float* beta  = (const float*)d_in[12];
    float* out = (float*)d_out;

    k_max<<<1, 1024>>>(event_times, event_types);
    k_prep<<<PREP_BLOCKS, 256>>>(event_types, emb, k1W, k1b, k2W, k2b,
                                 k3W, k3b, skipW, skipb);

    const int dil[NL] = {1, 2, 4, 8};
    for (int i = 0; i < NL; i++)
        k_fused<<<FUSED_GRID, 256>>>(i, dil[i], i == 0, gamma, beta);
    k_apply<<<(NPOS*NC + 255)/256, 256>>>(out, (NL-1) & 1);
}

// round 14
// speedup vs baseline: 1.4408x; 1.4408x over previous
#include <cuda_runtime.h>

#define BS 8
#define LQ 2049
#define NC 32
#define NH 16
#define KS 5
#define NL 4
#define NPOS (BS*LQ)            // 16392
#define TILE 16
#define NTILE 1025              // ceil(NPOS/16)
#define KA 584                  // 512 Gsum + 32 fsum + 32 enc + 1 one + 7 pad
#define KQ (KA/4)               // 146
#define TILE_ELEMS (KA*NC)      // 18688
#define ASTRIDE 596             // padded A row stride

#define BUILD_BLOCKS 2049       // NPOS*NC/256
#define MLPB 321                // per-layer MLP blocks
#define WC_BLOCKS 292           // NL*TILE_ELEMS/256
#define PREP_BLOCKS (BUILD_BLOCKS + NL*MLPB + WC_BLOCKS)

// -------- device scratch --------
__device__ __align__(16) float g_times[BS*LQ];
__device__ __align__(16) float g_enc[NPOS*NC];
__device__ __align__(16) float g_raw[2][NTILE*TILE*NC];   // ping-pong
__device__ __align__(16) float g_H2[NL*NPOS*KS*NH];       // 21 MB, all layers
__device__ __align__(16) float g_Wc[NL*TILE_ELEMS];
__device__ __align__(16) float g_psum[NTILE*NC];
__device__ __align__(16) float g_psq[NTILE*NC];
__device__ __align__(16) float g_bn[2*NC];
__device__ int g_maxtype;

__device__ __forceinline__ float lrelu(float x) { return x >= 0.f ? x : 0.1f*x; }

__device__ __forceinline__ unsigned long long pack2(float v) {
    unsigned long long r;
    asm("mov.b64 %0, {%1, %1};" : "=l"(r) : "f"(v));
    return r;
}
__device__ __forceinline__ void fma2(unsigned long long& acc,
                                     unsigned long long a, unsigned long long w) {
    asm("fma.rn.f32x2 %0, %1, %2, %0;" : "+l"(acc) : "l"(a), "l"(w));
}

// -------- prep 1: max type, times --------
__global__ void k_max(const float* __restrict__ et, const int* __restrict__ types) {
    __shared__ int sm[1024];
    int t = threadIdx.x, m = 0;
    for (int i = t; i < BS*2048; i += 1024) m = max(m, types[i]);
    sm[t] = m;
    for (int s = 512; s > 0; s >>= 1) {
        __syncthreads();
        if (t < s) sm[t] = max(sm[t], sm[t+s]);
    }
    __syncthreads();
    if (t == 0) g_maxtype = sm[0];
    for (int i = t; i < NPOS; i += 1024) {
        int b = i / LQ, l = i - b*LQ;
        g_times[i] = (l == 0) ? 0.f : et[b*2048 + l - 1];
    }
}

// -------- prep 2 (merged): enc build | all-layer MLP | Wc build --------
__global__ __launch_bounds__(256) void k_prep(
        const int* __restrict__ ty, const float* __restrict__ emb,
        const float* __restrict__ k1W, const float* __restrict__ k1b,
        const float* __restrict__ k2W, const float* __restrict__ k2b,
        const float* __restrict__ k3W, const float* __restrict__ k3b,
        const float* __restrict__ skipW, const float* __restrict__ skipb) {
    int bid = blockIdx.x;
    int t = threadIdx.x;

    if (bid < BUILD_BLOCKS) {
        int idx = bid*256 + t;
        if (idx >= NPOS*NC) return;
        int pos = idx >> 5, c = idx & 31;
        int b = pos / LQ, l = pos - b*LQ;
        int tp = (l == 0) ? (g_maxtype + 1) : ty[b*2048 + l - 1];
        g_enc[idx] = (tp == 0) ? 0.f : emb[tp*NC + c];
        return;
    }
    if (bid < BUILD_BLOCKS + NL*MLPB) {
        int idx2 = bid - BUILD_BLOCKS;
        int layer = idx2 / MLPB;
        int blk = idx2 - layer*MLPB;
        int dil = 1 << layer;
        __shared__ float sk1[NH], sk1b[NH], sk2[NH*NH], sk2b[NH];
        if (t < NH) { sk1[t] = k1W[layer*NH + t]; sk1b[t] = k1b[layer*NH + t];
                      sk2b[t] = k2b[layer*NH + t]; }
        sk2[t] = k2W[layer*NH*NH + t];
        __syncthreads();
        int idx = blk*256 + t;
        if (idx >= NPOS*KS) return;
        int pos = idx / KS, k = idx - pos*KS;
        int b = pos / LQ, l = pos - b*LQ;
        float out[NH];
        bool valid = false;
        int j = l - k*dil;
        float tl = g_times[pos];
        if (j >= 0 && tl != 0.f) {
            float tj = g_times[b*LQ + j];
            if (tj != 0.f) {
                valid = true;
                float dt = tl - tj;
                float h1[NH];
                #pragma unroll
                for (int h = 0; h < NH; h++) h1[h] = lrelu(fmaf(dt, sk1[h], sk1b[h]));
                #pragma unroll
                for (int hh = 0; hh < NH; hh++) {
                    float s = sk2b[hh];
                    #pragma unroll
                    for (int x = 0; x < NH; x++) s = fmaf(h1[x], sk2[x*NH + hh], s);
                    out[hh] = lrelu(s);
                }
            }
        }
        if (!valid) {
            #pragma unroll
            for (int h = 0; h < NH; h++) out[h] = 0.f;
        }
        float* dst = g_H2 + (size_t)((layer*NPOS + pos)*KS + k)*NH;
        #pragma unroll
        for (int q = 0; q < 4; q++)
            *reinterpret_cast<float4*>(dst + 4*q) =
                make_float4(out[4*q], out[4*q+1], out[4*q+2], out[4*q+3]);
        return;
    }
    {
        int idx = (bid - BUILD_BLOCKS - NL*MLPB)*256 + t;
        if (idx >= NL*TILE_ELEMS) return;
        int layer = idx / TILE_ELEMS;
        int rem = idx - layer*TILE_ELEMS;
        int r = rem >> 5, d = rem & 31;
        float v;
        if (r < 512)      v = k3W[layer*16384 + r*32 + d];
        else if (r < 544) v = k3b[layer*1024 + (r-512)*32 + d];
        else if (r < 576) v = skipW[layer*1024 + (r-544)*32 + d];
        else if (r == 576) v = skipb[layer*32 + d];
        else v = 0.f;
        g_Wc[idx] = v;
    }
}

// -------- fused: one tile per block; phase A + 4-way-K f32x2 GEMM + BN partials
__global__ __launch_bounds__(256) void k_fused(int layer, int dil, int first) {
    __shared__ float s_bn[64];
    __shared__ __align__(16) float s_A[TILE*ASTRIDE];     // 38144 B
    __shared__ __align__(16) float s_red[TILE*NC];
    __shared__ __align__(16) float s_ps[TILE*NC], s_ps2[TILE*NC];
    int t = threadIdx.x;
    int lane = t & 31, warp = t >> 5;
    int tile = blockIdx.x;
    const float* raw_in = g_raw[(layer + 1) & 1];
    float* raw_out = g_raw[layer & 1];

    if (!first && t < 64) s_bn[t] = g_bn[t];
    __syncthreads();

    // ---- phase A: 8 warps x 2 positions; lane = channel c ----
    #pragma unroll
    for (int wp = 0; wp < 2; wp++) {
        int p = warp*2 + wp;
        int pos = tile*TILE + p;
        float G[NH];
        #pragma unroll
        for (int h = 0; h < NH; h++) G[h] = 0.f;
        float fs = 0.f, en = 0.f, one = 0.f;
        if (pos < NPOS) {
            one = 1.f;
            int b = pos / LQ, l = pos - b*LQ;
            float tl = g_times[pos];
            if (first) en = g_enc[pos*NC + lane];
            else {
                float v = fmaf(raw_in[pos*NC + lane], s_bn[lane], s_bn[32 + lane]);
                en = v >= 0.f ? v : 0.1f*v;
            }
            if (tl != 0.f) {
                const float* h2p = g_H2 + (size_t)((layer*NPOS + pos)*KS)*NH;
                for (int k = 0; k < KS; k++) {
                    int j = l - k*dil;
                    if (j < 0) break;
                    float tj = g_times[b*LQ + j];
                    if (tj != 0.f) {
                        int pj = pos - k*dil;
                        float g;
                        if (first) g = g_enc[pj*NC + lane];
                        else {
                            float v = fmaf(raw_in[pj*NC + lane], s_bn[lane], s_bn[32 + lane]);
                            g = v >= 0.f ? v : 0.1f*v;
                        }
                        fs += g;
                        float4 h0 = *reinterpret_cast<const float4*>(h2p + k*NH + 0);
                        float4 h1 = *reinterpret_cast<const float4*>(h2p + k*NH + 4);
                        float4 h2 = *reinterpret_cast<const float4*>(h2p + k*NH + 8);
                        float4 h3 = *reinterpret_cast<const float4*>(h2p + k*NH + 12);
                        G[0]  = fmaf(h0.x, g, G[0]);   G[1]  = fmaf(h0.y, g, G[1]);
                        G[2]  = fmaf(h0.z, g, G[2]);   G[3]  = fmaf(h0.w, g, G[3]);
                        G[4]  = fmaf(h1.x, g, G[4]);   G[5]  = fmaf(h1.y, g, G[5]);
                        G[6]  = fmaf(h1.z, g, G[6]);   G[7]  = fmaf(h1.w, g, G[7]);
                        G[8]  = fmaf(h2.x, g, G[8]);   G[9]  = fmaf(h2.y, g, G[9]);
                        G[10] = fmaf(h2.z, g, G[10]);  G[11] = fmaf(h2.w, g, G[11]);
                        G[12] = fmaf(h3.x, g, G[12]);  G[13] = fmaf(h3.y, g, G[13]);
                        G[14] = fmaf(h3.z, g, G[14]);  G[15] = fmaf(h3.w, g, G[15]);
                    }
                }
            }
        }
        float* row = s_A + p*ASTRIDE;
        #pragma unroll
        for (int h = 0; h < NH; h++) row[h*32 + lane] = G[h];
        row[512 + lane] = fs;
        row[544 + lane] = en;
        if (lane == 0) row[576] = one;
        if (lane < 7)  row[577 + lane] = 0.f;
    }
    __syncthreads();

    // ---- GEMM: 4-way K-split, 2 positions/thread (W reuse), packed f32x2 ----
    int tx = t & 7;            // d0 = 4*tx
    int pp = (t >> 3) & 7;     // positions 2*pp, 2*pp+1
    int ks = t >> 6;           // 0..3
    int p0 = 2*pp, p1 = 2*pp + 1;
    const float* Ap0 = s_A + p0*ASTRIDE + ks*KQ;
    const float* Ap1 = Ap0 + ASTRIDE;
    const float* Wl = g_Wc + layer*TILE_ELEMS + ks*KQ*NC + 4*tx;
    unsigned long long a00 = 0ULL, a01 = 0ULL;   // pos0: (d0,d1), (d2,d3)
    unsigned long long a10 = 0ULL, a11 = 0ULL;   // pos1
    #pragma unroll 4
    for (int kk = 0; kk < KQ/2; kk++) {          // 73 iterations
        float2 f0 = *reinterpret_cast<const float2*>(Ap0 + 2*kk);
        float2 f1 = *reinterpret_cast<const float2*>(Ap1 + 2*kk);
        ulonglong2 w0 = *reinterpret_cast<const ulonglong2*>(Wl + (2*kk + 0)*NC);
        ulonglong2 w1 = *reinterpret_cast<const ulonglong2*>(Wl + (2*kk + 1)*NC);
        unsigned long long q;
        q = pack2(f0.x); fma2(a00, q, w0.x); fma2(a01, q, w0.y);
        q = pack2(f1.x); fma2(a10, q, w0.x); fma2(a11, q, w0.y);
        q = pack2(f0.y); fma2(a00, q, w1.x); fma2(a01, q, w1.y);
        q = pack2(f1.y); fma2(a10, q, w1.x); fma2(a11, q, w1.y);
    }
    float v00, v01, v02, v03, v10, v11, v12, v13;
    asm("mov.b64 {%0, %1}, %2;" : "=f"(v00), "=f"(v01) : "l"(a00));
    asm("mov.b64 {%0, %1}, %2;" : "=f"(v02), "=f"(v03) : "l"(a01));
    asm("mov.b64 {%0, %1}, %2;" : "=f"(v10), "=f"(v11) : "l"(a10));
    asm("mov.b64 {%0, %1}, %2;" : "=f"(v12), "=f"(v13) : "l"(a11));

    // partial staging: ks1->s_ps, ks2->s_ps2, ks3->s_red (reuse BN buffers)
    if (ks == 1) {
        *reinterpret_cast<float4*>(&s_ps[p0*32 + 4*tx]) = make_float4(v00, v01, v02, v03);
        *reinterpret_cast<float4*>(&s_ps[p1*32 + 4*tx]) = make_float4(v10, v11, v12, v13);
    } else if (ks == 2) {
        *reinterpret_cast<float4*>(&s_ps2[p0*32 + 4*tx]) = make_float4(v00, v01, v02, v03);
        *reinterpret_cast<float4*>(&s_ps2[p1*32 + 4*tx]) = make_float4(v10, v11, v12, v13);
    } else if (ks == 3) {
        *reinterpret_cast<float4*>(&s_red[p0*32 + 4*tx]) = make_float4(v00, v01, v02, v03);
        *reinterpret_cast<float4*>(&s_red[p1*32 + 4*tx]) = make_float4(v10, v11, v12, v13);
    }
    __syncthreads();
    if (ks == 0) {
        #pragma unroll
        for (int q = 0; q < 2; q++) {
            int p = (q == 0) ? p0 : p1;
            float r0 = (q == 0) ? v00 : v10, r1 = (q == 0) ? v01 : v11;
            float r2 = (q == 0) ? v02 : v12, r3 = (q == 0) ? v03 : v13;
            float4 e1 = *reinterpret_cast<const float4*>(&s_ps [p*32 + 4*tx]);
            float4 e2 = *reinterpret_cast<const float4*>(&s_ps2[p*32 + 4*tx]);
            float4 e3 = *reinterpret_cast<const float4*>(&s_red[p*32 + 4*tx]);
            r0 = ((r0 + e1.x) + e2.x) + e3.x;
            r1 = ((r1 + e1.y) + e2.y) + e3.y;
            r2 = ((r2 + e1.z) + e2.z) + e3.z;
            r3 = ((r3 + e1.w) + e2.w) + e3.w;
            *reinterpret_cast<float4*>(raw_out + (size_t)(tile*TILE + p)*NC + 4*tx) =
                make_float4(r0, r1, r2, r3);
            *reinterpret_cast<float4*>(&s_ps [p*32 + 4*tx]) = make_float4(r0, r1, r2, r3);
            *reinterpret_cast<float4*>(&s_ps2[p*32 + 4*tx]) =
                make_float4(r0*r0, r1*r1, r2*r2, r3*r3);
        }
    }
    __syncthreads();
    if (t < 32) {
        float s = 0.f, s2 = 0.f;
        #pragma unroll
        for (int r = 0; r < TILE; r++) { s += s_ps[r*32 + t]; s2 += s_ps2[r*32 + t]; }
        g_psum[tile*32 + t] = s;
        g_psq [tile*32 + t] = s2;
    }
}

// -------- BN stats: 1024 threads, 32-way parallel per channel --------
__global__ __launch_bounds__(1024) void k_stats(int layer, const float* __restrict__ gamma,
                        const float* __restrict__ beta) {
    __shared__ float ss[32][33], ss2[32][33];
    int t = threadIdx.x;
    int r = t >> 5, n = t & 31;
    float s = 0.f, s2 = 0.f;
    #pragma unroll 4
    for (int b = r; b < NTILE; b += 32) {
        s += g_psum[b*32 + n];
        s2 += g_psq[b*32 + n];
    }
    ss[r][n] = s; ss2[r][n] = s2;
    __syncthreads();
    if (t < 32) {
        float fs = 0.f, fs2 = 0.f;
        #pragma unroll
        for (int i = 0; i < 32; i++) { fs += ss[i][t]; fs2 += ss2[i][t]; }
        float inv = 1.0f / (float)NPOS;
        float mu = fs * inv;
        float var = fs2 * inv - mu*mu;
        float scale = rsqrtf(var + 1e-5f) * gamma[layer*32 + t];
        g_bn[t]      = scale;
        g_bn[32 + t] = beta[layer*32 + t] - mu*scale;
    }
}

// -------- final apply: BN + leaky ReLU -> output --------
__global__ void k_apply(float* dst, int buf) {
    int idx = blockIdx.x*blockDim.x + threadIdx.x;
    if (idx >= NPOS*NC) return;
    int n = idx & 31;
    float v = fmaf(g_raw[buf][idx], g_bn[n], g_bn[32 + n]);
    dst[idx] = v >= 0.f ? v : 0.1f*v;
}

extern "C" void kernel_launch(void* const* d_in, const int* in_sizes, int n_in,
                              void* d_out, int out_size) {
    const float* event_times = (const float*)d_in[0];
    const int*   event_types = (const int*)  d_in[1];
    const float* emb   = (const float*)d_in[2];
    const float* k1W   = (const float*)d_in[3];
    const float* k1b   = (const float*)d_in[4];
    const float* k2W   = (const float*)d_in[5];
    const float* k2b   = (const float*)d_in[6];
    const float* k3W   = (const float*)d_in[7];
    const float* k3b   = (const float*)d_in[8];
    const float* skipW = (const float*)d_in[9];
    const float* skipb = (const float*)d_in[10];
    const float* gamma = (const float*)d_in[11];
    const float* beta  = (const float*)d_in[12];
    float* out = (float*)d_out;

    k_max<<<1, 1024>>>(event_times, event_types);
    k_prep<<<PREP_BLOCKS, 256>>>(event_types, emb, k1W, k1b, k2W, k2b,
                                 k3W, k3b, skipW, skipb);

    const int dil[NL] = {1, 2, 4, 8};
    for (int i = 0; i < NL; i++) {
        k_fused<<<NTILE, 256>>>(i, dil[i], i == 0);
        k_stats<<<1, 1024>>>(i, gamma, beta);
    }
    k_apply<<<(NPOS*NC + 255)/256, 256>>>(out, (NL-1) & 1);
}

// round 15
// speedup vs baseline: 1.4735x; 1.0226x over previous
#include <cuda_runtime.h>

#define BS 8
#define LQ 2049
#define NC 32
#define NH 16
#define KS 5
#define NL 4
#define NPOS (BS*LQ)            // 16392
#define TILE 16
#define NTILE 1025              // ceil(NPOS/16)
#define KA 584                  // 512 Gsum + 32 fsum + 32 enc + 1 one + 7 pad
#define KQ (KA/4)               // 146
#define TILE_ELEMS (KA*NC)      // 18688
#define ASTRIDE 596             // padded A row stride

#define BUILD_BLOCKS 2049       // NPOS*NC/256
#define MLPB 321                // per-layer MLP blocks
#define WC_BLOCKS 292           // NL*TILE_ELEMS/256
#define PREP_BLOCKS (BUILD_BLOCKS + NL*MLPB + WC_BLOCKS)

// -------- device scratch --------
__device__ __align__(16) float g_times[BS*LQ];
__device__ __align__(16) float g_enc[NPOS*NC];
__device__ __align__(16) float g_raw[2][NTILE*TILE*NC];   // ping-pong
__device__ __align__(16) float g_H2[NL*NPOS*KS*NH];       // 21 MB, all layers
__device__ __align__(16) float g_Wc[NL*TILE_ELEMS];
__device__ __align__(16) float g_psum[NTILE*NC];
__device__ __align__(16) float g_psq[NTILE*NC];
__device__ __align__(16) float g_fs[NC];                  // per-channel sum
__device__ __align__(16) float g_fs2[NC];                 // per-channel sumsq
__device__ int g_maxtype;

__device__ __forceinline__ float lrelu(float x) { return x >= 0.f ? x : 0.1f*x; }

__device__ __forceinline__ unsigned long long pack2(float v) {
    unsigned long long r;
    asm("mov.b64 %0, {%1, %1};" : "=l"(r) : "f"(v));
    return r;
}
__device__ __forceinline__ void fma2(unsigned long long& acc,
                                     unsigned long long a, unsigned long long w) {
    asm("fma.rn.f32x2 %0, %1, %2, %0;" : "+l"(acc) : "l"(a), "l"(w));
}

// -------- prep 1: max type, times --------
__global__ void k_max(const float* __restrict__ et, const int* __restrict__ types) {
    __shared__ int sm[1024];
    int t = threadIdx.x, m = 0;
    for (int i = t; i < BS*2048; i += 1024) m = max(m, types[i]);
    sm[t] = m;
    for (int s = 512; s > 0; s >>= 1) {
        __syncthreads();
        if (t < s) sm[t] = max(sm[t], sm[t+s]);
    }
    __syncthreads();
    if (t == 0) g_maxtype = sm[0];
    for (int i = t; i < NPOS; i += 1024) {
        int b = i / LQ, l = i - b*LQ;
        g_times[i] = (l == 0) ? 0.f : et[b*2048 + l - 1];
    }
}

// -------- prep 2 (merged): enc build | all-layer MLP | Wc build --------
__global__ __launch_bounds__(256) void k_prep(
        const int* __restrict__ ty, const float* __restrict__ emb,
        const float* __restrict__ k1W, const float* __restrict__ k1b,
        const float* __restrict__ k2W, const float* __restrict__ k2b,
        const float* __restrict__ k3W, const float* __restrict__ k3b,
        const float* __restrict__ skipW, const float* __restrict__ skipb) {
    int bid = blockIdx.x;
    int t = threadIdx.x;

    if (bid < BUILD_BLOCKS) {
        int idx = bid*256 + t;
        if (idx >= NPOS*NC) return;
        int pos = idx >> 5, c = idx & 31;
        int b = pos / LQ, l = pos - b*LQ;
        int tp = (l == 0) ? (g_maxtype + 1) : ty[b*2048 + l - 1];
        g_enc[idx] = (tp == 0) ? 0.f : emb[tp*NC + c];
        return;
    }
    if (bid < BUILD_BLOCKS + NL*MLPB) {
        int idx2 = bid - BUILD_BLOCKS;
        int layer = idx2 / MLPB;
        int blk = idx2 - layer*MLPB;
        int dil = 1 << layer;
        __shared__ float sk1[NH], sk1b[NH], sk2[NH*NH], sk2b[NH];
        if (t < NH) { sk1[t] = k1W[layer*NH + t]; sk1b[t] = k1b[layer*NH + t];
                      sk2b[t] = k2b[layer*NH + t]; }
        sk2[t] = k2W[layer*NH*NH + t];
        __syncthreads();
        int idx = blk*256 + t;
        if (idx >= NPOS*KS) return;
        int pos = idx / KS, k = idx - pos*KS;
        int b = pos / LQ, l = pos - b*LQ;
        float out[NH];
        bool valid = false;
        int j = l - k*dil;
        float tl = g_times[pos];
        if (j >= 0 && tl != 0.f) {
            float tj = g_times[b*LQ + j];
            if (tj != 0.f) {
                valid = true;
                float dt = tl - tj;
                float h1[NH];
                #pragma unroll
                for (int h = 0; h < NH; h++) h1[h] = lrelu(fmaf(dt, sk1[h], sk1b[h]));
                #pragma unroll
                for (int hh = 0; hh < NH; hh++) {
                    float s = sk2b[hh];
                    #pragma unroll
                    for (int x = 0; x < NH; x++) s = fmaf(h1[x], sk2[x*NH + hh], s);
                    out[hh] = lrelu(s);
                }
            }
        }
        if (!valid) {
            #pragma unroll
            for (int h = 0; h < NH; h++) out[h] = 0.f;
        }
        float* dst = g_H2 + (size_t)((layer*NPOS + pos)*KS + k)*NH;
        #pragma unroll
        for (int q = 0; q < 4; q++)
            *reinterpret_cast<float4*>(dst + 4*q) =
                make_float4(out[4*q], out[4*q+1], out[4*q+2], out[4*q+3]);
        return;
    }
    {
        int idx = (bid - BUILD_BLOCKS - NL*MLPB)*256 + t;
        if (idx >= NL*TILE_ELEMS) return;
        int layer = idx / TILE_ELEMS;
        int rem = idx - layer*TILE_ELEMS;
        int r = rem >> 5, d = rem & 31;
        float v;
        if (r < 512)      v = k3W[layer*16384 + r*32 + d];
        else if (r < 544) v = k3b[layer*1024 + (r-512)*32 + d];
        else if (r < 576) v = skipW[layer*1024 + (r-544)*32 + d];
        else if (r == 576) v = skipb[layer*32 + d];
        else v = 0.f;
        g_Wc[idx] = v;
    }
}

// -------- fused: one tile per block; phase A + 4-way-K f32x2 GEMM + BN partials
// BN coefficients for the PREVIOUS layer are computed in-preamble from g_fs/g_fs2.
__global__ __launch_bounds__(256) void k_fused(int layer, int dil, int first,
        const float* __restrict__ gamma, const float* __restrict__ beta) {
    __shared__ float s_bn[64];
    __shared__ __align__(16) float s_A[TILE*ASTRIDE];     // 38144 B
    __shared__ __align__(16) float s_red[TILE*NC];
    __shared__ __align__(16) float s_ps[TILE*NC], s_ps2[TILE*NC];
    int t = threadIdx.x;
    int lane = t & 31, warp = t >> 5;
    int tile = blockIdx.x;
    const float* raw_in = g_raw[(layer + 1) & 1];
    float* raw_out = g_raw[layer & 1];

    if (!first && t < 32) {
        float inv = 1.0f / (float)NPOS;
        float mu = g_fs[t] * inv;
        float var = g_fs2[t] * inv - mu*mu;
        float scale = rsqrtf(var + 1e-5f) * gamma[(layer-1)*32 + t];
        s_bn[t]      = scale;
        s_bn[32 + t] = beta[(layer-1)*32 + t] - mu*scale;
    }
    __syncthreads();

    // ---- phase A: 8 warps x 2 positions; lane = channel c ----
    #pragma unroll
    for (int wp = 0; wp < 2; wp++) {
        int p = warp*2 + wp;
        int pos = tile*TILE + p;
        float G[NH];
        #pragma unroll
        for (int h = 0; h < NH; h++) G[h] = 0.f;
        float fs = 0.f, en = 0.f, one = 0.f;
        if (pos < NPOS) {
            one = 1.f;
            int b = pos / LQ, l = pos - b*LQ;
            float tl = g_times[pos];
            if (first) en = g_enc[pos*NC + lane];
            else {
                float v = fmaf(raw_in[pos*NC + lane], s_bn[lane], s_bn[32 + lane]);
                en = v >= 0.f ? v : 0.1f*v;
            }
            if (tl != 0.f) {
                const float* h2p = g_H2 + (size_t)((layer*NPOS + pos)*KS)*NH;
                for (int k = 0; k < KS; k++) {
                    int j = l - k*dil;
                    if (j < 0) break;
                    float tj = g_times[b*LQ + j];
                    if (tj != 0.f) {
                        int pj = pos - k*dil;
                        float g;
                        if (first) g = g_enc[pj*NC + lane];
                        else {
                            float v = fmaf(raw_in[pj*NC + lane], s_bn[lane], s_bn[32 + lane]);
                            g = v >= 0.f ? v : 0.1f*v;
                        }
                        fs += g;
                        float4 h0 = *reinterpret_cast<const float4*>(h2p + k*NH + 0);
                        float4 h1 = *reinterpret_cast<const float4*>(h2p + k*NH + 4);
                        float4 h2 = *reinterpret_cast<const float4*>(h2p + k*NH + 8);
                        float4 h3 = *reinterpret_cast<const float4*>(h2p + k*NH + 12);
                        G[0]  = fmaf(h0.x, g, G[0]);   G[1]  = fmaf(h0.y, g, G[1]);
                        G[2]  = fmaf(h0.z, g, G[2]);   G[3]  = fmaf(h0.w, g, G[3]);
                        G[4]  = fmaf(h1.x, g, G[4]);   G[5]  = fmaf(h1.y, g, G[5]);
                        G[6]  = fmaf(h1.z, g, G[6]);   G[7]  = fmaf(h1.w, g, G[7]);
                        G[8]  = fmaf(h2.x, g, G[8]);   G[9]  = fmaf(h2.y, g, G[9]);
                        G[10] = fmaf(h2.z, g, G[10]);  G[11] = fmaf(h2.w, g, G[11]);
                        G[12] = fmaf(h3.x, g, G[12]);  G[13] = fmaf(h3.y, g, G[13]);
                        G[14] = fmaf(h3.z, g, G[14]);  G[15] = fmaf(h3.w, g, G[15]);
                    }
                }
            }
        }
        float* row = s_A + p*ASTRIDE;
        #pragma unroll
        for (int h = 0; h < NH; h++) row[h*32 + lane] = G[h];
        row[512 + lane] = fs;
        row[544 + lane] = en;
        if (lane == 0) row[576] = one;
        if (lane < 7)  row[577 + lane] = 0.f;
    }
    __syncthreads();

    // ---- GEMM: 4-way K-split, 2 positions/thread (W reuse), packed f32x2 ----
    int tx = t & 7;            // d0 = 4*tx
    int pp = (t >> 3) & 7;     // positions 2*pp, 2*pp+1
    int ks = t >> 6;           // 0..3
    int p0 = 2*pp, p1 = 2*pp + 1;
    const float* Ap0 = s_A + p0*ASTRIDE + ks*KQ;
    const float* Ap1 = Ap0 + ASTRIDE;
    const float* Wl = g_Wc + layer*TILE_ELEMS + ks*KQ*NC + 4*tx;
    unsigned long long a00 = 0ULL, a01 = 0ULL;   // pos0: (d0,d1), (d2,d3)
    unsigned long long a10 = 0ULL, a11 = 0ULL;   // pos1
    #pragma unroll 4
    for (int kk = 0; kk < KQ/2; kk++) {          // 73 iterations
        float2 f0 = *reinterpret_cast<const float2*>(Ap0 + 2*kk);
        float2 f1 = *reinterpret_cast<const float2*>(Ap1 + 2*kk);
        ulonglong2 w0 = *reinterpret_cast<const ulonglong2*>(Wl + (2*kk + 0)*NC);
        ulonglong2 w1 = *reinterpret_cast<const ulonglong2*>(Wl + (2*kk + 1)*NC);
        unsigned long long q;
        q = pack2(f0.x); fma2(a00, q, w0.x); fma2(a01, q, w0.y);
        q = pack2(f1.x); fma2(a10, q, w0.x); fma2(a11, q, w0.y);
        q = pack2(f0.y); fma2(a00, q, w1.x); fma2(a01, q, w1.y);
        q = pack2(f1.y); fma2(a10, q, w1.x); fma2(a11, q, w1.y);
    }
    float v00, v01, v02, v03, v10, v11, v12, v13;
    asm("mov.b64 {%0, %1}, %2;" : "=f"(v00), "=f"(v01) : "l"(a00));
    asm("mov.b64 {%0, %1}, %2;" : "=f"(v02), "=f"(v03) : "l"(a01));
    asm("mov.b64 {%0, %1}, %2;" : "=f"(v10), "=f"(v11) : "l"(a10));
    asm("mov.b64 {%0, %1}, %2;" : "=f"(v12), "=f"(v13) : "l"(a11));

    // partial staging: ks1->s_ps, ks2->s_ps2, ks3->s_red (reuse BN buffers)
    if (ks == 1) {
        *reinterpret_cast<float4*>(&s_ps[p0*32 + 4*tx]) = make_float4(v00, v01, v02, v03);
        *reinterpret_cast<float4*>(&s_ps[p1*32 + 4*tx]) = make_float4(v10, v11, v12, v13);
    } else if (ks == 2) {
        *reinterpret_cast<float4*>(&s_ps2[p0*32 + 4*tx]) = make_float4(v00, v01, v02, v03);
        *reinterpret_cast<float4*>(&s_ps2[p1*32 + 4*tx]) = make_float4(v10, v11, v12, v13);
    } else if (ks == 3) {
        *reinterpret_cast<float4*>(&s_red[p0*32 + 4*tx]) = make_float4(v00, v01, v02, v03);
        *reinterpret_cast<float4*>(&s_red[p1*32 + 4*tx]) = make_float4(v10, v11, v12, v13);
    }
    __syncthreads();
    if (ks == 0) {
        #pragma unroll
        for (int q = 0; q < 2; q++) {
            int p = (q == 0) ? p0 : p1;
            float r0 = (q == 0) ? v00 : v10, r1 = (q == 0) ? v01 : v11;
            float r2 = (q == 0) ? v02 : v12, r3 = (q == 0) ? v03 : v13;
            float4 e1 = *reinterpret_cast<const float4*>(&s_ps [p*32 + 4*tx]);
            float4 e2 = *reinterpret_cast<const float4*>(&s_ps2[p*32 + 4*tx]);
            float4 e3 = *reinterpret_cast<const float4*>(&s_red[p*32 + 4*tx]);
            r0 = ((r0 + e1.x) + e2.x) + e3.x;
            r1 = ((r1 + e1.y) + e2.y) + e3.y;
            r2 = ((r2 + e1.z) + e2.z) + e3.z;
            r3 = ((r3 + e1.w) + e2.w) + e3.w;
            *reinterpret_cast<float4*>(raw_out + (size_t)(tile*TILE + p)*NC + 4*tx) =
                make_float4(r0, r1, r2, r3);
            *reinterpret_cast<float4*>(&s_ps [p*32 + 4*tx]) = make_float4(r0, r1, r2, r3);
            *reinterpret_cast<float4*>(&s_ps2[p*32 + 4*tx]) =
                make_float4(r0*r0, r1*r1, r2*r2, r3*r3);
        }
    }
    __syncthreads();
    if (t < 32) {
        float s = 0.f, s2 = 0.f;
        #pragma unroll
        for (int r = 0; r < TILE; r++) { s += s_ps[r*32 + t]; s2 += s_ps2[r*32 + t]; }
        g_psum[tile*32 + t] = s;
        g_psq [tile*32 + t] = s2;
    }
}

// -------- BN stats: one block per channel, 256-thread strided + fixed tree ----
__global__ __launch_bounds__(256) void k_statsA() {
    __shared__ float ss[256], ss2[256];
    int ch = blockIdx.x;       // 0..31
    int t = threadIdx.x;
    float s = 0.f, s2 = 0.f;
    #pragma unroll
    for (int b = t; b < NTILE; b += 256) {
        s += g_psum[b*32 + ch];
        s2 += g_psq[b*32 + ch];
    }
    ss[t] = s; ss2[t] = s2;
    for (int st = 128; st > 0; st >>= 1) {
        __syncthreads();
        if (t < st) { ss[t] += ss[t+st]; ss2[t] += ss2[t+st]; }
    }
    if (t == 0) { g_fs[ch] = ss[0]; g_fs2[ch] = ss2[0]; }
}

// -------- final apply: BN (computed in-preamble) + leaky ReLU -> output ------
__global__ void k_apply(float* dst, int buf,
                        const float* __restrict__ gamma, const float* __restrict__ beta) {
    __shared__ float s_bn[64];
    int t = threadIdx.x;
    if (t < 32) {
        float inv = 1.0f / (float)NPOS;
        float mu = g_fs[t] * inv;
        float var = g_fs2[t] * inv - mu*mu;
        float scale = rsqrtf(var + 1e-5f) * gamma[(NL-1)*32 + t];
        s_bn[t]      = scale;
        s_bn[32 + t] = beta[(NL-1)*32 + t] - mu*scale;
    }
    __syncthreads();
    int idx = blockIdx.x*blockDim.x + t;
    if (idx >= NPOS*NC) return;
    int n = idx & 31;
    float v = fmaf(g_raw[buf][idx], s_bn[n], s_bn[32 + n]);
    dst[idx] = v >= 0.f ? v : 0.1f*v;
}

extern "C" void kernel_launch(void* const* d_in, const int* in_sizes, int n_in,
                              void* d_out, int out_size) {
    const float* event_times = (const float*)d_in[0];
    const int*   event_types = (const int*)  d_in[1];
    const float* emb   = (const float*)d_in[2];
    const float* k1W   = (const float*)d_in[3];
    const float* k1b   = (const float*)d_in[4];
    const float* k2W   = (const float*)d_in[5];
    const float* k2b   = (const float*)d_in[6];
    const float* k3W   = (const float*)d_in[7];
    const float* k3b   = (const float*)d_in[8];
    const float* skipW = (const float*)d_in[9];
    const float* skipb = (const float*)d_in[10];
    const float* gamma = (const float*)d_in[11];
    const float* beta  = (const float*)d_in[12];
    float* out = (float*)d_out;

    k_max<<<1, 1024>>>(event_times, event_types);
    k_prep<<<PREP_BLOCKS, 256>>>(event_types, emb, k1W, k1b, k2W, k2b,
                                 k3W, k3b, skipW, skipb);

    const int dil[NL] = {1, 2, 4, 8};
    for (int i = 0; i < NL; i++) {
        k_fused<<<NTILE, 256>>>(i, dil[i], i == 0, gamma, beta);
        k_statsA<<<NC, 256>>>();
    }
    k_apply<<<(NPOS*NC + 255)/256, 256>>>(out, (NL-1) & 1, gamma, beta);
}